// round 8
// baseline (speedup 1.0000x reference)
#include <cuda_runtime.h>
#include <cstdint>
#include <math.h>

#define BLOCKT  64            // 2 warps per block; each warp owns 32 samples
#define KDIM    784
#define KPAD    800
#define SEGK    100           // K columns per segment
#define SEGPAD  108           // padded row stride (words): conflict-free LDS, 16B-aligned
#define NSEG    8             // 8*100 = 800 (784 valid)
#define RING    3             // ring slots per warp
#define STAGE   (32*SEGPAD)   // 3456 floats: one slot (32 rows x 108)

// smem floats: mbars(16) + xs[2][3][STAGE] + w1s[800*4] + sw[240] = 24192 floats = 94.5KB
#define SMEM_FLOATS (16 + 2*RING*STAGE + KPAD*4 + 240)

__device__ __forceinline__ void mbar_init1(unsigned addr) {
    asm volatile("mbarrier.init.shared.b64 [%0], 1;" :: "r"(addr) : "memory");
}
__device__ __forceinline__ void mbar_expect(unsigned addr, unsigned tx) {
    asm volatile("mbarrier.arrive.expect_tx.shared.b64 _, [%0], %1;"
                 :: "r"(addr), "r"(tx) : "memory");
}
__device__ __forceinline__ void mbar_wait(unsigned addr, unsigned parity) {
    asm volatile(
        "{\n\t.reg .pred P;\n\t"
        "WAIT_%=:\n\t"
        "mbarrier.try_wait.parity.acquire.cta.shared::cta.b64 P, [%0], %1, 0x989680;\n\t"
        "@P bra.uni DONE_%=;\n\t"
        "bra.uni WAIT_%=;\n\t"
        "DONE_%=:\n\t}"
        :: "r"(addr), "r"(parity) : "memory");
}
__device__ __forceinline__ void bulk_g2s(unsigned dst, const float* src,
                                         unsigned nbytes, unsigned mbar) {
    asm volatile(
        "cp.async.bulk.shared::cta.global.mbarrier::complete_tx::bytes [%0], [%1], %2, [%3];"
        :: "r"(dst), "l"(src), "r"(nbytes), "r"(mbar) : "memory");
}

__global__ void __launch_bounds__(BLOCKT) qhybrid_kernel(
    const float* __restrict__ x,
    const float* __restrict__ W1, const float* __restrict__ b1,
    const float* __restrict__ qw,
    const float* __restrict__ W2, const float* __restrict__ b2,
    const float* __restrict__ W3, const float* __restrict__ b3,
    float* __restrict__ out, int B)
{
    extern __shared__ float smem[];
    float* xs  = smem + 16;                    // [2][3][32][108]
    float* w1s = xs + 2 * RING * STAGE;        // [800][4]
    float* sw  = w1s + KPAD * 4;               // small weights

    const int tid  = threadIdx.x;
    const int lane = tid & 31;
    const int wrp  = tid >> 5;                 // 0..1

    const long sbase = (long)blockIdx.x * BLOCKT + wrp * 32;
    const long srowg = sbase + lane;
    const bool rvalid = (srowg < (long)B);
    const float* srow = x + srowg * (long)KDIM;

    // number of valid rows in this warp's 32-sample group
    int nvalid = (int)((long)B - sbase);
    nvalid = nvalid < 0 ? 0 : (nvalid > 32 ? 32 : nvalid);

    float* wstage = xs + wrp * RING * STAGE;
    const unsigned smem_u  = (unsigned)__cvta_generic_to_shared(smem);
    const unsigned mbar0   = smem_u + wrp * RING * 8;           // 3 mbars per warp
    const unsigned wstage_u = (unsigned)__cvta_generic_to_shared(wstage);
    const unsigned lanedst  = wstage_u + (unsigned)(lane * SEGPAD * 4);

    // ---- init this warp's mbarriers ----
    if (lane == 0) {
        mbar_init1(mbar0);
        mbar_init1(mbar0 + 8);
        mbar_init1(mbar0 + 16);
    }
    __syncwarp();

    // ---- issue segment s into ring slot (s % RING) ----
    #define ISSUE_SEG(s) do {                                                 \
        const int _s = (s);                                                   \
        const unsigned _bytes = (_s == NSEG - 1) ? 336u : 400u;               \
        const unsigned _mb = mbar0 + (unsigned)((_s % RING) * 8);             \
        if (lane == 0) mbar_expect(_mb, _bytes * (unsigned)nvalid);           \
        __syncwarp();                                                         \
        if (rvalid) bulk_g2s(lanedst + (unsigned)((_s % RING) * STAGE * 4),   \
                             srow + _s * SEGK, _bytes, _mb);                  \
    } while (0)

    // ---- prologue: 3 segments in flight ----
    ISSUE_SEG(0);
    ISSUE_SEG(1);
    ISSUE_SEG(2);

    // ---- preload W1 (zero-padded rows 784..799) + small weights ----
    for (int r = tid; r < KPAD; r += BLOCKT) {
        float4 v = make_float4(0.f, 0.f, 0.f, 0.f);
        if (r < KDIM) v = __ldg((const float4*)W1 + r);
        ((float4*)w1s)[r] = v;
    }
    // b1@0(4) qw@4(8) W2@12(128) b2@140(32) W3@172(64) b3@236(2)
    if (tid < 4)  sw[tid]      = b1[tid];
    if (tid < 8)  sw[4 + tid]  = qw[tid];
    for (int j = tid; j < 128; j += BLOCKT) sw[12 + j] = W2[j];
    if (tid < 32) sw[140 + tid] = b2[tid];
    for (int j = tid; j < 64; j += BLOCKT)  sw[172 + j] = W3[j];
    if (tid < 2)  sw[236 + tid] = b3[tid];
    __syncthreads();   // publish w1s/sw (only block-wide barrier)

    float acc[4] = {0.f, 0.f, 0.f, 0.f};

    // ---- per-segment compute: NCH float4 chunks of this lane's row ----
    #define COMPUTE_SEG(s, NCH) do {                                          \
        const float* _xr = wstage + ((s) % RING) * STAGE + lane * SEGPAD;     \
        const float* _wb = w1s + (s) * SEGK * 4;                              \
        _Pragma("unroll")                                                     \
        for (int _c = 0; _c < (NCH); _c++) {                                  \
            float4 _xv = *(const float4*)(_xr + _c * 4);                      \
            const float* _wp = _wb + _c * 16;                                 \
            float4 _wa = *(const float4*)(_wp);                               \
            float4 _w2 = *(const float4*)(_wp + 4);                           \
            float4 _w3 = *(const float4*)(_wp + 8);                           \
            float4 _w4 = *(const float4*)(_wp + 12);                          \
            acc[0]=fmaf(_xv.x,_wa.x,acc[0]); acc[1]=fmaf(_xv.x,_wa.y,acc[1]); \
            acc[2]=fmaf(_xv.x,_wa.z,acc[2]); acc[3]=fmaf(_xv.x,_wa.w,acc[3]); \
            acc[0]=fmaf(_xv.y,_w2.x,acc[0]); acc[1]=fmaf(_xv.y,_w2.y,acc[1]); \
            acc[2]=fmaf(_xv.y,_w2.z,acc[2]); acc[3]=fmaf(_xv.y,_w2.w,acc[3]); \
            acc[0]=fmaf(_xv.z,_w3.x,acc[0]); acc[1]=fmaf(_xv.z,_w3.y,acc[1]); \
            acc[2]=fmaf(_xv.z,_w3.z,acc[2]); acc[3]=fmaf(_xv.z,_w3.w,acc[3]); \
            acc[0]=fmaf(_xv.w,_w4.x,acc[0]); acc[1]=fmaf(_xv.w,_w4.y,acc[1]); \
            acc[2]=fmaf(_xv.w,_w4.z,acc[2]); acc[3]=fmaf(_xv.w,_w4.w,acc[3]); \
        }                                                                     \
    } while (0)

    // ---- mainloop: segments 0..6 (25 chunks each) ----
    #pragma unroll 1
    for (int s = 0; s < NSEG - 1; s++) {
        mbar_wait(mbar0 + (unsigned)((s % RING) * 8), (unsigned)((s / RING) & 1));
        COMPUTE_SEG(s, 25);
        const int sp = s + RING;
        if (sp < NSEG) ISSUE_SEG(sp);     // reuse the slot just consumed
    }
    // ---- tail: segment 7 (cols 700..783 -> 21 chunks) ----
    {
        const int s = NSEG - 1;
        mbar_wait(mbar0 + (unsigned)((s % RING) * 8), (unsigned)((s / RING) & 1));
        COMPUTE_SEG(s, 21);
    }

    // ---- angles = relu(pre + b1) ----
    float cq[4], sq[4];
    #pragma unroll
    for (int q = 0; q < 4; q++) {
        float ang = fmaxf(acc[q] + sw[q], 0.f);
        __sincosf(0.5f * ang, &sq[q], &cq[q]);
    }

    // ---- 4-qubit statevector in registers ----
    float re[16], im[16];
    #pragma unroll
    for (int i = 0; i < 16; i++) {
        float m = 1.f;
        #pragma unroll
        for (int q = 0; q < 4; q++) m *= ((i >> (3 - q)) & 1) ? sq[q] : cq[q];
        int k = __popc(i) & 3;  // phase (-i)^k
        re[i] = (k == 0) ? m : ((k == 2) ? -m : 0.f);
        im[i] = (k == 1) ? -m : ((k == 3) ? m : 0.f);
    }

    // ---- BasicEntanglerLayers: RX(w[l,q]) then CNOT ring ----
    #pragma unroll
    for (int l = 0; l < 2; l++) {
        #pragma unroll
        for (int q = 0; q < 4; q++) {
            float cg, sg;
            __sincosf(0.5f * sw[4 + l * 4 + q], &sg, &cg);
            const int mask = 8 >> q;
            #pragma unroll
            for (int i = 0; i < 16; i++) {
                if (i & mask) continue;
                const int i1 = i | mask;
                float r0 = re[i], ii0 = im[i], r1 = re[i1], ii1 = im[i1];
                re[i]  = fmaf(cg, r0,  sg * ii1);
                im[i]  = fmaf(cg, ii0, -sg * r1);
                re[i1] = fmaf(cg, r1,  sg * ii0);
                im[i1] = fmaf(cg, ii1, -sg * r0);
            }
        }
        #pragma unroll
        for (int q = 0; q < 4; q++) {
            const int cmask = 8 >> q;
            const int tmask = 8 >> ((q + 1) & 3);
            #pragma unroll
            for (int i = 0; i < 16; i++) {
                if ((i & cmask) && !(i & tmask)) {
                    const int j = i | tmask;
                    float t = re[i]; re[i] = re[j]; re[j] = t;
                    t = im[i]; im[i] = im[j]; im[j] = t;
                }
            }
        }
    }

    // ---- <Z_q> expectation values ----
    float ez[4] = {0.f, 0.f, 0.f, 0.f};
    #pragma unroll
    for (int i = 0; i < 16; i++) {
        float p = re[i] * re[i] + im[i] * im[i];
        #pragma unroll
        for (int q = 0; q < 4; q++)
            ez[q] += ((i >> (3 - q)) & 1) ? -p : p;
    }
    #pragma unroll
    for (int q = 0; q < 4; q++)
        if (!(ez[q] == ez[q])) ez[q] = 0.f;  // NaN -> 0 (matches reference)

    // ---- post = relu(ez@W2 + b2); logits = post@W3 + b3; softmax ----
    float l0 = sw[236], l1 = sw[237];
    #pragma unroll
    for (int j = 0; j < 32; j++) {
        float pj = sw[140 + j];
        #pragma unroll
        for (int q = 0; q < 4; q++)
            pj = fmaf(ez[q], sw[12 + q * 32 + j], pj);
        pj = fmaxf(pj, 0.f);
        l0 = fmaf(pj, sw[172 + j * 2],     l0);
        l1 = fmaf(pj, sw[172 + j * 2 + 1], l1);
    }
    float mx = fmaxf(l0, l1);
    float e0 = __expf(l0 - mx);
    float e1 = __expf(l1 - mx);
    float inv = 1.f / (e0 + e1);

    if (rvalid) {
        float2 o = make_float2(e0 * inv, e1 * inv);
        *(float2*)(out + srowg * 2) = o;
    }
}

extern "C" void kernel_launch(void* const* d_in, const int* in_sizes, int n_in,
                              void* d_out, int out_size) {
    const float* x  = (const float*)d_in[0];
    const float* W1 = (const float*)d_in[1];
    const float* b1 = (const float*)d_in[2];
    const float* qw = (const float*)d_in[3];
    const float* W2 = (const float*)d_in[4];
    const float* b2 = (const float*)d_in[5];
    const float* W3 = (const float*)d_in[6];
    const float* b3 = (const float*)d_in[7];
    float* out = (float*)d_out;

    int B = in_sizes[0] / KDIM;
    int grid = (B + BLOCKT - 1) / BLOCKT;           // 1024 blocks
    size_t smem_bytes = SMEM_FLOATS * sizeof(float);  // ~94.5 KB
    cudaFuncSetAttribute(qhybrid_kernel,
                         cudaFuncAttributeMaxDynamicSharedMemorySize,
                         (int)smem_bytes);
    qhybrid_kernel<<<grid, BLOCKT, smem_bytes>>>(x, W1, b1, qw, W2, b2, W3, b3, out, B);
}

// round 9
// speedup vs baseline: 1.4719x; 1.4719x over previous
#include <cuda_runtime.h>
#include <cuda.h>
#include <cstdint>
#include <math.h>

#define BLOCKT  64            // 64 threads = 64 samples per block
#define KDIM    784
#define KPAD    800
#define TILE_K  32            // 32 cols * 4B = 128B rows (SW128 box)
#define NT      25            // 25*32 = 800 (TMA zero-fills cols >= 784)
#define RING    4
#define TILE_B  8192          // 64 rows * 128B
// smem bytes: xs 4*8192 = 32768 | mbars @32768 (32B) | w1s @32800 (12800B) | sw @45600 (960B)
#define SMEM_BYTES 46560

__device__ __forceinline__ void mbar_init1(unsigned addr) {
    asm volatile("mbarrier.init.shared.b64 [%0], 1;" :: "r"(addr) : "memory");
}
__device__ __forceinline__ void mbar_expect(unsigned addr, unsigned tx) {
    asm volatile("mbarrier.arrive.expect_tx.shared.b64 _, [%0], %1;"
                 :: "r"(addr), "r"(tx) : "memory");
}
__device__ __forceinline__ void mbar_wait(unsigned addr, unsigned parity) {
    asm volatile(
        "{\n\t.reg .pred P;\n\t"
        "WAIT_%=:\n\t"
        "mbarrier.try_wait.parity.acquire.cta.shared::cta.b64 P, [%0], %1, 0x989680;\n\t"
        "@P bra.uni DONE_%=;\n\t"
        "bra.uni WAIT_%=;\n\t"
        "DONE_%=:\n\t}"
        :: "r"(addr), "r"(parity) : "memory");
}
__device__ __forceinline__ void tma_2d(unsigned dst, const CUtensorMap* tm,
                                       int cx, int cy, unsigned mbar) {
    asm volatile(
        "cp.async.bulk.tensor.2d.shared::cta.global.tile.mbarrier::complete_tx::bytes "
        "[%0], [%1, {%2, %3}], [%4];"
        :: "r"(dst), "l"(tm), "r"(cx), "r"(cy), "r"(mbar) : "memory");
}

__global__ void __launch_bounds__(BLOCKT) qhybrid_kernel(
    const __grid_constant__ CUtensorMap tmap,
    const float* __restrict__ W1, const float* __restrict__ b1,
    const float* __restrict__ qw,
    const float* __restrict__ W2, const float* __restrict__ b2,
    const float* __restrict__ W3, const float* __restrict__ b3,
    float* __restrict__ out, int B)
{
    extern __shared__ __align__(1024) char smem[];
    char*  xs  = smem;                          // [4][64 rows][128B] swizzled
    float* w1s = (float*)(smem + 32800);        // [800][4]
    float* sw  = (float*)(smem + 45600);        // small weights

    const int tid = threadIdx.x;
    const unsigned smem_u = (unsigned)__cvta_generic_to_shared(smem);
    const unsigned mbar0  = smem_u + 32768u;    // 4 mbars * 8B

    // ---- tid 0: init ring mbarriers, kick off 3 tiles immediately ----
    if (tid == 0) {
        mbar_init1(mbar0);
        mbar_init1(mbar0 + 8);
        mbar_init1(mbar0 + 16);
        mbar_init1(mbar0 + 24);
        asm volatile("fence.proxy.async.shared::cta;" ::: "memory");
        const int rowbase = blockIdx.x * BLOCKT;
        #pragma unroll
        for (int kt = 0; kt < 3; kt++) {
            mbar_expect(mbar0 + kt * 8, TILE_B);
            tma_2d(smem_u + kt * TILE_B, &tmap, kt * TILE_K, rowbase, mbar0 + kt * 8);
        }
    }

    // ---- preload W1 (zero-padded rows 784..799) + small weights ----
    for (int r = tid; r < KPAD; r += BLOCKT) {
        float4 v = make_float4(0.f, 0.f, 0.f, 0.f);
        if (r < KDIM) v = __ldg((const float4*)W1 + r);
        ((float4*)w1s)[r] = v;
    }
    // b1@0(4) qw@4(8) W2@12(128) b2@140(32) W3@172(64) b3@236(2)
    if (tid < 4)  sw[tid]      = b1[tid];
    if (tid < 8)  sw[4 + tid]  = qw[tid];
    for (int j = tid; j < 128; j += BLOCKT) sw[12 + j] = W2[j];
    if (tid < 32) sw[140 + tid] = b2[tid];
    for (int j = tid; j < 64; j += BLOCKT)  sw[172 + j] = W3[j];
    if (tid < 2)  sw[236 + tid] = b3[tid];
    __syncthreads();    // publish w1s/sw; orders mbar init for all threads

    float acc[4] = {0.f, 0.f, 0.f, 0.f};
    const int rsw = (tid & 7);          // swizzle key for this thread's row
    char* xrow_base = xs + tid * 128;   // + slot*TILE_B

    // ---- GEMM mainloop: TMA ring, one barrier per iter ----
    #pragma unroll 1
    for (int kt = 0; kt < NT; kt++) {
        mbar_wait(mbar0 + (unsigned)((kt & 3) * 8), (unsigned)((kt >> 2) & 1));
        __syncthreads();   // all warps done with tile kt-1's slot reads; tile kt visible

        if (tid == 0) {
            const int kp = kt + 3;
            if (kp < NT) {
                const unsigned mb = mbar0 + (unsigned)((kp & 3) * 8);
                mbar_expect(mb, TILE_B);
                tma_2d(smem_u + (unsigned)((kp & 3) * TILE_B), &tmap,
                       kp * TILE_K, blockIdx.x * BLOCKT, mb);
            }
        }

        // compute tile kt: 8 swizzled float4 chunks of this thread's row
        const char* xr = xrow_base + (kt & 3) * TILE_B;
        const float* wb = w1s + kt * TILE_K * 4;
        #pragma unroll
        for (int j = 0; j < 8; j++) {
            float4 xv = *(const float4*)(xr + ((j ^ rsw) << 4));
            const float* wp = wb + j * 16;
            float4 wa = *(const float4*)(wp);
            float4 w2 = *(const float4*)(wp + 4);
            float4 w3 = *(const float4*)(wp + 8);
            float4 w4 = *(const float4*)(wp + 12);
            acc[0]=fmaf(xv.x,wa.x,acc[0]); acc[1]=fmaf(xv.x,wa.y,acc[1]);
            acc[2]=fmaf(xv.x,wa.z,acc[2]); acc[3]=fmaf(xv.x,wa.w,acc[3]);
            acc[0]=fmaf(xv.y,w2.x,acc[0]); acc[1]=fmaf(xv.y,w2.y,acc[1]);
            acc[2]=fmaf(xv.y,w2.z,acc[2]); acc[3]=fmaf(xv.y,w2.w,acc[3]);
            acc[0]=fmaf(xv.z,w3.x,acc[0]); acc[1]=fmaf(xv.z,w3.y,acc[1]);
            acc[2]=fmaf(xv.z,w3.z,acc[2]); acc[3]=fmaf(xv.z,w3.w,acc[3]);
            acc[0]=fmaf(xv.w,w4.x,acc[0]); acc[1]=fmaf(xv.w,w4.y,acc[1]);
            acc[2]=fmaf(xv.w,w4.z,acc[2]); acc[3]=fmaf(xv.w,w4.w,acc[3]);
        }
    }

    // ---- angles = relu(pre + b1) ----
    float cq[4], sq[4];
    #pragma unroll
    for (int q = 0; q < 4; q++) {
        float ang = fmaxf(acc[q] + sw[q], 0.f);
        __sincosf(0.5f * ang, &sq[q], &cq[q]);
    }

    // ---- 4-qubit statevector in registers ----
    float re[16], im[16];
    #pragma unroll
    for (int i = 0; i < 16; i++) {
        float m = 1.f;
        #pragma unroll
        for (int q = 0; q < 4; q++) m *= ((i >> (3 - q)) & 1) ? sq[q] : cq[q];
        int k = __popc(i) & 3;  // phase (-i)^k
        re[i] = (k == 0) ? m : ((k == 2) ? -m : 0.f);
        im[i] = (k == 1) ? -m : ((k == 3) ? m : 0.f);
    }

    // ---- BasicEntanglerLayers: RX(w[l,q]) then CNOT ring ----
    #pragma unroll
    for (int l = 0; l < 2; l++) {
        #pragma unroll
        for (int q = 0; q < 4; q++) {
            float cg, sg;
            __sincosf(0.5f * sw[4 + l * 4 + q], &sg, &cg);
            const int mask = 8 >> q;
            #pragma unroll
            for (int i = 0; i < 16; i++) {
                if (i & mask) continue;
                const int i1 = i | mask;
                float r0 = re[i], ii0 = im[i], r1 = re[i1], ii1 = im[i1];
                re[i]  = fmaf(cg, r0,  sg * ii1);
                im[i]  = fmaf(cg, ii0, -sg * r1);
                re[i1] = fmaf(cg, r1,  sg * ii0);
                im[i1] = fmaf(cg, ii1, -sg * r0);
            }
        }
        #pragma unroll
        for (int q = 0; q < 4; q++) {
            const int cmask = 8 >> q;
            const int tmask = 8 >> ((q + 1) & 3);
            #pragma unroll
            for (int i = 0; i < 16; i++) {
                if ((i & cmask) && !(i & tmask)) {
                    const int j = i | tmask;
                    float t = re[i]; re[i] = re[j]; re[j] = t;
                    t = im[i]; im[i] = im[j]; im[j] = t;
                }
            }
        }
    }

    // ---- <Z_q> expectation values ----
    float ez[4] = {0.f, 0.f, 0.f, 0.f};
    #pragma unroll
    for (int i = 0; i < 16; i++) {
        float p = re[i] * re[i] + im[i] * im[i];
        #pragma unroll
        for (int q = 0; q < 4; q++)
            ez[q] += ((i >> (3 - q)) & 1) ? -p : p;
    }
    #pragma unroll
    for (int q = 0; q < 4; q++)
        if (!(ez[q] == ez[q])) ez[q] = 0.f;  // NaN -> 0 (matches reference)

    // ---- post = relu(ez@W2 + b2); logits = post@W3 + b3; softmax ----
    float l0 = sw[236], l1 = sw[237];
    #pragma unroll
    for (int j = 0; j < 32; j++) {
        float pj = sw[140 + j];
        #pragma unroll
        for (int q = 0; q < 4; q++)
            pj = fmaf(ez[q], sw[12 + q * 32 + j], pj);
        pj = fmaxf(pj, 0.f);
        l0 = fmaf(pj, sw[172 + j * 2],     l0);
        l1 = fmaf(pj, sw[172 + j * 2 + 1], l1);
    }
    float mx = fmaxf(l0, l1);
    float e0 = __expf(l0 - mx);
    float e1 = __expf(l1 - mx);
    float inv = 1.f / (e0 + e1);

    long sg = (long)blockIdx.x * BLOCKT + tid;
    if (sg < (long)B) {
        float2 o = make_float2(e0 * inv, e1 * inv);
        *(float2*)(out + sg * 2) = o;
    }
}

typedef CUresult (*PFN_encodeTiled)(
    CUtensorMap*, CUtensorMapDataType, cuuint32_t, void*,
    const cuuint64_t*, const cuuint64_t*, const cuuint32_t*, const cuuint32_t*,
    CUtensorMapInterleave, CUtensorMapSwizzle, CUtensorMapL2promotion,
    CUtensorMapFloatOOBfill);

extern "C" void kernel_launch(void* const* d_in, const int* in_sizes, int n_in,
                              void* d_out, int out_size) {
    const float* x  = (const float*)d_in[0];
    const float* W1 = (const float*)d_in[1];
    const float* b1 = (const float*)d_in[2];
    const float* qw = (const float*)d_in[3];
    const float* W2 = (const float*)d_in[4];
    const float* b2 = (const float*)d_in[5];
    const float* W3 = (const float*)d_in[6];
    const float* b3 = (const float*)d_in[7];
    float* out = (float*)d_out;

    int B = in_sizes[0] / KDIM;

    // Build tensor map for x: [B rows, 784 cols] fp32, box [32, 64], SW128.
    // Driver symbol fetched via cudart (no -lcuda needed).
    PFN_encodeTiled encode = nullptr;
    cudaDriverEntryPointQueryResult qres;
    cudaGetDriverEntryPoint("cuTensorMapEncodeTiled", (void**)&encode,
                            cudaEnableDefault, &qres);
    CUtensorMap tmap;
    cuuint64_t dims[2]    = {(cuuint64_t)KDIM, (cuuint64_t)B};
    cuuint64_t strides[1] = {(cuuint64_t)KDIM * sizeof(float)};
    cuuint32_t box[2]     = {TILE_K, BLOCKT};
    cuuint32_t estr[2]    = {1, 1};
    encode(&tmap, CU_TENSOR_MAP_DATA_TYPE_FLOAT32, 2, (void*)x,
           dims, strides, box, estr,
           CU_TENSOR_MAP_INTERLEAVE_NONE, CU_TENSOR_MAP_SWIZZLE_128B,
           CU_TENSOR_MAP_L2_PROMOTION_L2_128B, CU_TENSOR_MAP_FLOAT_OOB_FILL_NONE);

    int grid = (B + BLOCKT - 1) / BLOCKT;           // 1024 blocks
    cudaFuncSetAttribute(qhybrid_kernel,
                         cudaFuncAttributeMaxDynamicSharedMemorySize, SMEM_BYTES);
    qhybrid_kernel<<<grid, BLOCKT, SMEM_BYTES>>>(tmap, W1, b1, qw, W2, b2, W3, b3, out, B);
}